// round 14
// baseline (speedup 1.0000x reference)
#include <cuda_runtime.h>

#define B_ 256
#define T_ 512
#define D_ 128
#define U_ 128
#define C_ 64

typedef unsigned long long ull;

__device__ __forceinline__ ull pk2(float x, float y) {
    ull r; asm("mov.b64 %0, {%1,%2};" : "=l"(r) : "f"(x), "f"(y)); return r;
}
__device__ __forceinline__ void upk2(ull v, float& x, float& y) {
    asm("mov.b64 {%0,%1}, %2;" : "=f"(x), "=f"(y) : "l"(v));
}
__device__ __forceinline__ ull ffma2(ull a, ull b, ull c) {
    ull d; asm("fma.rn.f32x2 %0, %1, %2, %3;" : "=l"(d) : "l"(a), "l"(b), "l"(c)); return d;
}
__device__ __forceinline__ float tanh_fast(float x) {
    float y; asm("tanh.approx.f32 %0, %1;" : "=f"(y) : "f"(x)); return y;
}

// smem float offsets
#define ST_ROW   136                    // ring row 544B = 34x16
#define SM_WCP   0                      // float2[64][64]  = 32KB
#define SM_HIST  8192                   // 32*136          = 17KB
#define SM_HBUF  12544                  // 2*2048          = 16KB
#define SM_XBUF  16640                  // 2*2048          = 16KB
#define SM_TOTF  20736                  // 82944 B per CTA (2 CTAs/SM)

// ---------------------------------------------------------------------------
// MEGA v2: one CTA per chain, 256 CTAs (one wave @ occ 2), 192 threads.
// Rec role (128 thr): recurrence, W2[:,j] in regs, bar.sync 1,128 per step,
//   h from smem hbuf, y into 32-deep ring.
// Head role (64 thr): per block boundary i:
//   H-GEMM blk i+1 = tanh(xbuf @ W1 + b1) -> hbuf  (W1 from L1/L2),
//   stage X blk i+2 -> xbuf, out-GEMM blk i-1 from ring -> out.
// Role placement alternates with (bid>>2)&1 so co-resident CTAs put their
// head warps on different SMSP pairs (fma-pipe balance).
// ---------------------------------------------------------------------------
__global__ void __launch_bounds__(192, 2)
k_mega(const float* __restrict__ X,  const float* __restrict__ W1,
       const float* __restrict__ b1, const float* __restrict__ W2,
       const float* __restrict__ b2, const float* __restrict__ Wc,
       const float* __restrict__ bc, float* __restrict__ out)
{
    extern __shared__ float sm[];
    float2* WcP  = (float2*)(sm + SM_WCP);
    float*  hist = sm + SM_HIST;
    float*  hbuf = sm + SM_HBUF;
    float*  xbuf = sm + SM_XBUF;

    const int tid   = threadIdx.x;
    const int chain = blockIdx.x;
    const float* Xc = X + (size_t)chain * (T_*128);

    // role selection: alternate head warps between {4,5} and {2,3}
    const int  head_lo = (blockIdx.x >> 2) & 1;
    const bool is_head = head_lo ? (tid >= 64 && tid < 128) : (tid >= 128);

    // stage Wc pair-interleaved (all threads)
    for (int idx = tid; idx < 4096; idx += 192) {
        int kp = idx >> 6, c = idx & 63;
        WcP[idx] = make_float2(__ldg(Wc + (size_t)(2*kp)   * 64 + c),
                               __ldg(Wc + (size_t)(2*kp+1) * 64 + c));
    }
    // stage X block 0 -> xbuf[0] (all threads)
    for (int idx = tid; idx < 512; idx += 192)
        *(float4*)(xbuf + idx*4) = *(const float4*)(Xc + idx*4);

    if (!is_head) {
        // ========================= RECURRENCE ROLE =========================
        const int j = head_lo ? (tid < 64 ? tid : tid - 64) : tid;

        ull w[64];
        #pragma unroll
        for (int p = 0; p < 64; p++)
            w[p] = pk2(__ldg(W2 + (size_t)(2*p)*128 + j),
                       __ldg(W2 + (size_t)(2*p+1)*128 + j));
        const float b2v = __ldg(b2 + j);
        const int sidx = (j & 63) + (j >> 6) * 68;

        hist[31 * ST_ROW + sidx] = 0.0f;          // y_{-1}
        __syncthreads();                          // P1
        __syncthreads();                          // P2 (head built H blk0)

        #pragma unroll 1
        for (int i = 0; i <= 32; i++) {
            if (i < 32) {
                const int t0 = i * 16;
                const float* hb = hbuf + (i & 1) * 2048;
                #pragma unroll 4
                for (int u = 0; u < 16; u++) {
                    const int t = t0 + u;
                    float hv = hb[u * 128 + j];

                    const float* sb = hist + (((t + 31) & 31) * ST_ROW);
                    ull a0 = 0ULL, a1 = 0ULL, a2 = 0ULL, a3 = 0ULL;
                    #pragma unroll
                    for (int p = 0; p < 8; p++) {
                        ulonglong2 s0  = *(const ulonglong2*)(sb + 8*p);
                        ulonglong2 s1  = *(const ulonglong2*)(sb + 68 + 8*p);
                        a0 = ffma2(s0.x,  w[4*p+0],  a0);
                        a1 = ffma2(s0.y,  w[4*p+1],  a1);
                        a2 = ffma2(s1.x,  w[32+4*p], a2);
                        a3 = ffma2(s1.y,  w[33+4*p], a3);
                        ulonglong2 s0b = *(const ulonglong2*)(sb + 8*p + 4);
                        ulonglong2 s1b = *(const ulonglong2*)(sb + 68 + 8*p + 4);
                        a0 = ffma2(s0b.x, w[4*p+2],  a0);
                        a1 = ffma2(s0b.y, w[4*p+3],  a1);
                        a2 = ffma2(s1b.x, w[34+4*p], a2);
                        a3 = ffma2(s1b.y, w[35+4*p], a3);
                    }
                    float x0,y0,x1,y1,x2,y2,x3,y3;
                    upk2(a0,x0,y0); upk2(a1,x1,y1);
                    upk2(a2,x2,y2); upk2(a3,x3,y3);
                    float s = ((x0+y0)+(x1+y1)) + ((x2+y2)+(x3+y3)) + b2v;
                    float yv = hv + tanh_fast(s);

                    hist[(t & 31) * ST_ROW + sidx] = yv;
                    asm volatile("bar.sync 1, 128;" ::: "memory");
                }
            }
            __syncthreads();                      // block boundary
        }
    } else {
        // ============================ HEAD ROLE ============================
        const int h  = head_lo ? (tid - 64) : (tid - 128);   // 0..63
        const int hr = (h >> 4) * 4;              // H-GEMM rows (4 of 16)
        const int hc = (h & 15) * 8;              // H-GEMM cols (8 of 128)
        const int rr = (h >> 4) * 4;              // out rows (4 of 16)
        const int cc = (h & 15) * 4;              // out cols (4 of 64)

        float bb1[8], bbc[4];
        #pragma unroll
        for (int c = 0; c < 8; c++) bb1[c] = __ldg(b1 + hc + c);
        #pragma unroll
        for (int c = 0; c < 4; c++) bbc[c] = __ldg(bc + cc + c);

        __syncthreads();                          // P1

        // H-GEMM for a 16x128 block: xbuf[src] @ W1 -> hbuf[dst]
        auto h_gemm = [&](int srcbuf, int dstbuf) {
            const float* xs = xbuf + srcbuf * 2048;
            float*       hd = hbuf + dstbuf * 2048;
            ull A[4][8];
            #pragma unroll
            for (int r = 0; r < 4; r++)
                #pragma unroll
                for (int c = 0; c < 8; c++) A[r][c] = 0ULL;

            const float* wa = W1 + hc;            // row 0, my cols
            float4 a0 = *(const float4*)(wa);
            float4 a1 = *(const float4*)(wa + 4);
            float4 b0 = *(const float4*)(wa + 128);
            float4 b1 = *(const float4*)(wa + 132);

            #pragma unroll 2
            for (int kp = 0; kp < 64; kp++) {
                float4 na0, na1, nb0, nb1;
                if (kp < 63) {
                    const float* wn = W1 + (size_t)(2*kp+2)*128 + hc;
                    na0 = *(const float4*)(wn);
                    na1 = *(const float4*)(wn + 4);
                    nb0 = *(const float4*)(wn + 128);
                    nb1 = *(const float4*)(wn + 132);
                }
                ull wv[8];
                wv[0] = pk2(a0.x, b0.x); wv[1] = pk2(a0.y, b0.y);
                wv[2] = pk2(a0.z, b0.z); wv[3] = pk2(a0.w, b0.w);
                wv[4] = pk2(a1.x, b1.x); wv[5] = pk2(a1.y, b1.y);
                wv[6] = pk2(a1.z, b1.z); wv[7] = pk2(a1.w, b1.w);
                #pragma unroll
                for (int r = 0; r < 4; r++) {
                    ull xv = *(const ull*)(xs + (hr + r)*128 + 2*kp);
                    #pragma unroll
                    for (int c = 0; c < 8; c++)
                        A[r][c] = ffma2(xv, wv[c], A[r][c]);
                }
                a0 = na0; a1 = na1; b0 = nb0; b1 = nb1;
            }
            #pragma unroll
            for (int r = 0; r < 4; r++) {
                float4 o; float x, y;
                float4 o2;
                upk2(A[r][0], x, y); o.x  = tanh_fast(x + y + bb1[0]);
                upk2(A[r][1], x, y); o.y  = tanh_fast(x + y + bb1[1]);
                upk2(A[r][2], x, y); o.z  = tanh_fast(x + y + bb1[2]);
                upk2(A[r][3], x, y); o.w  = tanh_fast(x + y + bb1[3]);
                upk2(A[r][4], x, y); o2.x = tanh_fast(x + y + bb1[4]);
                upk2(A[r][5], x, y); o2.y = tanh_fast(x + y + bb1[5]);
                upk2(A[r][6], x, y); o2.z = tanh_fast(x + y + bb1[6]);
                upk2(A[r][7], x, y); o2.w = tanh_fast(x + y + bb1[7]);
                *(float4*)(hd + (hr + r)*128 + hc)     = o;
                *(float4*)(hd + (hr + r)*128 + hc + 4) = o2;
            }
        };

        // prologue: H blk0 -> hbuf[0]; stage X blk1 -> xbuf[1]
        h_gemm(0, 0);
        for (int kq = 0; kq < 8; kq++) {
            int idx = h + 64 * kq;
            *(float4*)(xbuf + 2048 + idx*4) =
                *(const float4*)(Xc + 2048 + idx*4);
        }
        __syncthreads();                          // P2

        #pragma unroll 1
        for (int i = 0; i <= 32; i++) {
            // (a) H-GEMM block i+1
            if (i + 1 < 32)
                h_gemm((i + 1) & 1, (i + 1) & 1);

            // (b) stage X block i+2 -> xbuf[i&1]
            if (i + 2 < 32) {
                const float* src = Xc + (size_t)(i + 2) * 2048;
                float*       dst = xbuf + (i & 1) * 2048;
                #pragma unroll
                for (int kq = 0; kq < 8; kq++) {
                    int idx = h + 64 * kq;
                    *(float4*)(dst + idx*4) = *(const float4*)(src + idx*4);
                }
            }

            // (c) out-GEMM block i-1 from the ring
            if (i >= 1) {
                const int t0h = (i - 1) * 16;
                const float* yr[4];
                #pragma unroll
                for (int r = 0; r < 4; r++)
                    yr[r] = hist + (((t0h + rr + r) & 31) * ST_ROW);

                ull acc[4][4];
                #pragma unroll
                for (int r = 0; r < 4; r++)
                    #pragma unroll
                    for (int c = 0; c < 4; c++) acc[r][c] = 0ULL;

                #pragma unroll 4
                for (int kp = 0; kp < 64; kp++) {
                    const int off = (kp < 32) ? (2*kp) : (68 + 2*(kp-32));
                    ulonglong2 w0 = *(const ulonglong2*)(WcP + kp*64 + cc);
                    ulonglong2 w1 = *(const ulonglong2*)(WcP + kp*64 + cc + 2);
                    #pragma unroll
                    for (int r = 0; r < 4; r++) {
                        ull yv = *(const ull*)(yr[r] + off);
                        acc[r][0] = ffma2(yv, w0.x, acc[r][0]);
                        acc[r][1] = ffma2(yv, w0.y, acc[r][1]);
                        acc[r][2] = ffma2(yv, w1.x, acc[r][2]);
                        acc[r][3] = ffma2(yv, w1.y, acc[r][3]);
                    }
                }
                #pragma unroll
                for (int r = 0; r < 4; r++) {
                    float4 o; float x, y;
                    upk2(acc[r][0], x, y); o.x = x + y + bbc[0];
                    upk2(acc[r][1], x, y); o.y = x + y + bbc[1];
                    upk2(acc[r][2], x, y); o.z = x + y + bbc[2];
                    upk2(acc[r][3], x, y); o.w = x + y + bbc[3];
                    *(float4*)(out + ((size_t)chain * T_ + t0h + rr + r) * 64 + cc) = o;
                }
            }
            __syncthreads();                      // block boundary
        }
    }
}

extern "C" void kernel_launch(void* const* d_in, const int* in_sizes, int n_in,
                              void* d_out, int out_size) {
    (void)in_sizes; (void)n_in; (void)out_size;
    const float* X  = (const float*)d_in[0];
    const float* W1 = (const float*)d_in[1];
    const float* b1 = (const float*)d_in[2];
    const float* W2 = (const float*)d_in[3];
    const float* b2 = (const float*)d_in[4];
    const float* Wc = (const float*)d_in[5];
    const float* bc = (const float*)d_in[6];
    float* out = (float*)d_out;

    cudaFuncSetAttribute(k_mega, cudaFuncAttributeMaxDynamicSharedMemorySize,
                         SM_TOTF * 4);
    k_mega<<<B_, 192, SM_TOTF * 4>>>(X, W1, b1, W2, b2, Wc, bc, out);
}

// round 15
// speedup vs baseline: 1.6628x; 1.6628x over previous
#include <cuda_runtime.h>

#define B_ 256
#define T_ 512
#define D_ 128
#define U_ 128
#define C_ 64
#define M_ (B_*T_)

// padded by 16 rows so head H-preload of the (nonexistent) block 32 is safe
__device__ float g_H[(size_t)(M_ + 16) * U_];

typedef unsigned long long ull;

__device__ __forceinline__ ull pk2(float x, float y) {
    ull r; asm("mov.b64 %0, {%1,%2};" : "=l"(r) : "f"(x), "f"(y)); return r;
}
__device__ __forceinline__ void upk2(ull v, float& x, float& y) {
    asm("mov.b64 {%0,%1}, %2;" : "=f"(x), "=f"(y) : "l"(v));
}
__device__ __forceinline__ ull ffma2(ull a, ull b, ull c) {
    ull d; asm("fma.rn.f32x2 %0, %1, %2, %3;" : "=l"(d) : "l"(a), "l"(b), "l"(c)); return d;
}
__device__ __forceinline__ float tanh_fast(float x) {
    float y; asm("tanh.approx.f32 %0, %1;" : "=f"(y) : "f"(x)); return y;
}

// ---------------------------------------------------------------------------
// K1: H = tanh(X @ W1 + b1). Proven config (107.7us).
// ---------------------------------------------------------------------------
__global__ void __launch_bounds__(256, 2)
k1_in_gemm(const float* __restrict__ X, const float* __restrict__ W1,
           const float* __restrict__ b1)
{
    extern __shared__ float smem[];
    float2* Wp = (float2*)smem;
    float*  Xs = smem + 16384;
    const int tid = threadIdx.x;
    const int m0 = blockIdx.x * 64;

    {
        const int c4 = (tid & 31) * 4;
        const int kp0 = tid >> 5;
        #pragma unroll
        for (int pass = 0; pass < 8; pass++) {
            int kp = kp0 + pass * 8;
            float4 a = *(const float4*)(W1 + (size_t)(2*kp)   * 128 + c4);
            float4 b = *(const float4*)(W1 + (size_t)(2*kp+1) * 128 + c4);
            float2* w = Wp + kp*128 + c4;
            w[0] = make_float2(a.x, b.x);
            w[1] = make_float2(a.y, b.y);
            w[2] = make_float2(a.z, b.z);
            w[3] = make_float2(a.w, b.w);
        }
    }
    {
        const int q  = (tid & 31) * 4;
        const int r0 = tid >> 5;
        #pragma unroll
        for (int pass = 0; pass < 8; pass++) {
            int row = r0 + pass * 8;
            *(float4*)(Xs + row*128 + q) =
                *(const float4*)(X + (size_t)(m0+row)*128 + q);
        }
    }
    __syncthreads();

    const int tc = tid & 31;
    const int tr = tid >> 5;
    ull acc[8][4];
    #pragma unroll
    for (int i = 0; i < 8; i++)
        #pragma unroll
        for (int c = 0; c < 4; c++) acc[i][c] = 0ULL;

    const float*  xbase = Xs + tr * 8 * 128;
    const float2* wbase = Wp + tc * 4;

    #pragma unroll 8
    for (int kp = 0; kp < 64; kp++) {
        ulonglong2 wv0 = *(const ulonglong2*)(wbase + (size_t)kp*128);
        ulonglong2 wv1 = *(const ulonglong2*)(wbase + (size_t)kp*128 + 2);
        #pragma unroll
        for (int i = 0; i < 8; i++) {
            ull xp = *(const ull*)(xbase + i*128 + 2*kp);
            acc[i][0] = ffma2(xp, wv0.x, acc[i][0]);
            acc[i][1] = ffma2(xp, wv0.y, acc[i][1]);
            acc[i][2] = ffma2(xp, wv1.x, acc[i][2]);
            acc[i][3] = ffma2(xp, wv1.y, acc[i][3]);
        }
    }

    float bb[4];
    #pragma unroll
    for (int c = 0; c < 4; c++) bb[c] = __ldg(b1 + tc*4 + c);

    #pragma unroll
    for (int i = 0; i < 8; i++) {
        int row = m0 + tr*8 + i;
        float4 o; float x, y;
        upk2(acc[i][0], x, y); o.x = tanh_fast(x + y + bb[0]);
        upk2(acc[i][1], x, y); o.y = tanh_fast(x + y + bb[1]);
        upk2(acc[i][2], x, y); o.z = tanh_fast(x + y + bb[2]);
        upk2(acc[i][3], x, y); o.w = tanh_fast(x + y + bb[3]);
        *(float4*)(g_H + (size_t)row*128 + tc*4) = o;
    }
}

// ---------------------------------------------------------------------------
// K2 v7 = R12 winner + serial-path trims:
//  - h for step u+1 prefetched into a register BEFORE the per-step barrier
//  - head out-GEMM kp loop split into two statically-offset halves
// One chain per CTA, 256 CTAs, 192 thr (128 rec + 64 head), 2 CTAs/SM.
// ---------------------------------------------------------------------------
#define ST_ROW 136   // 544B = 34x16; halves at float offsets 0 and 68

__global__ void __launch_bounds__(192, 2)
k2_fused(const float* __restrict__ W2, const float* __restrict__ b2,
         const float* __restrict__ Wc, const float* __restrict__ bc,
         float* __restrict__ out)
{
    extern __shared__ float sm[];
    float2* WcP  = (float2*)sm;            // [64 kp][64 c] float2 = 32KB
    float*  hist = sm + 8192;              // [32][ST_ROW] = 17.4KB
    float*  hbuf = sm + 8192 + 32*ST_ROW;  // [2][16*128] = 16KB

    const int tid = threadIdx.x;
    const int b   = blockIdx.x;

    // stage Wc pair-interleaved
    for (int idx = tid; idx < 64 * 64; idx += 192) {
        int kp = idx >> 6, c = idx & 63;
        WcP[kp * 64 + c] = make_float2(__ldg(Wc + (size_t)(2*kp)   * 64 + c),
                                       __ldg(Wc + (size_t)(2*kp+1) * 64 + c));
    }
    // stage H block 0 into hbuf[0]
    {
        const float* Hb = g_H + (size_t)b * (T_*128);
        for (int idx = tid; idx < 512; idx += 192)
            *(float4*)(hbuf + idx*4) = *(const float4*)(Hb + idx*4);
    }

    if (tid < 128) {
        // ================= RECURRENCE ROLE =================
        const int j = tid;

        ull w[64];
        #pragma unroll
        for (int p = 0; p < 64; p++)
            w[p] = pk2(__ldg(W2 + (size_t)(2*p)*128 + j),
                       __ldg(W2 + (size_t)(2*p+1)*128 + j));
        const float b2v = __ldg(b2 + j);

        const int sidx = (j & 63) + (j >> 6) * 68;
        hist[31 * ST_ROW + sidx] = 0.0f;      // y_{-1}
        __syncthreads();

        #pragma unroll 1
        for (int blk = 0; blk < 33; blk++) {
            if (blk < 32) {
                const int t0 = blk * 16;
                const float* hb = hbuf + (blk & 1) * 2048;
                float hv = hb[j];             // h for step u=0
                #pragma unroll 4
                for (int u = 0; u < 16; u++) {
                    const int t = t0 + u;

                    const float* sb = hist + (((t + 31) & 31) * ST_ROW);
                    ull a0 = 0ULL, a1 = 0ULL, a2 = 0ULL, a3 = 0ULL;
                    #pragma unroll
                    for (int p = 0; p < 8; p++) {
                        ulonglong2 s0  = *(const ulonglong2*)(sb + 8*p);
                        ulonglong2 s1  = *(const ulonglong2*)(sb + 68 + 8*p);
                        a0 = ffma2(s0.x,  w[4*p+0],  a0);
                        a1 = ffma2(s0.y,  w[4*p+1],  a1);
                        a2 = ffma2(s1.x,  w[32+4*p], a2);
                        a3 = ffma2(s1.y,  w[33+4*p], a3);
                        ulonglong2 s0b = *(const ulonglong2*)(sb + 8*p + 4);
                        ulonglong2 s1b = *(const ulonglong2*)(sb + 68 + 8*p + 4);
                        a0 = ffma2(s0b.x, w[4*p+2],  a0);
                        a1 = ffma2(s0b.y, w[4*p+3],  a1);
                        a2 = ffma2(s1b.x, w[34+4*p], a2);
                        a3 = ffma2(s1b.y, w[35+4*p], a3);
                    }
                    float x0,y0,x1,y1,x2,y2,x3,y3;
                    upk2(a0,x0,y0); upk2(a1,x1,y1);
                    upk2(a2,x2,y2); upk2(a3,x3,y3);
                    float s = ((x0+y0)+(x1+y1)) + ((x2+y2)+(x3+y3)) + b2v;
                    float yv = hv + tanh_fast(s);

                    // prefetch h for the NEXT step before the barrier
                    if (u < 15) hv = hb[(u + 1) * 128 + j];

                    hist[(t & 31) * ST_ROW + sidx] = yv;
                    asm volatile("bar.sync 1, 128;" ::: "memory");
                }
            }
            __syncthreads();   // block boundary (all 192)
        }
    } else {
        // ================= HEAD ROLE =================
        const int q  = tid - 128;            // 0..63
        const int r0 = (q >> 4) * 4;         // 4 rows of 16
        const int c4 = (q & 15) * 4;         // 4 cols of 64

        float bb[4];
        #pragma unroll
        for (int c = 0; c < 4; c++) bb[c] = __ldg(bc + c4 + c);

        const float* Hb = g_H + (size_t)b * (T_*128);

        __syncthreads();   // pairs with rec init sync

        #pragma unroll 1
        for (int blk = 0; blk < 33; blk++) {
            // (a) preload H block blk+1 into hbuf[(blk+1)&1]
            if (blk < 32) {
                float* dst = hbuf + ((blk + 1) & 1) * 2048;
                const float* src = Hb + (size_t)(blk + 1) * 16 * 128;
                #pragma unroll
                for (int i = 0; i < 8; i++) {
                    int idx = q + 64 * i;
                    *(float4*)(dst + idx*4) = *(const float4*)(src + idx*4);
                }
            }
            // (b) out-GEMM for block blk-1 from the ring (two static halves)
            if (blk > 0) {
                const int t0h = (blk - 1) * 16;
                const float* yr[4];
                #pragma unroll
                for (int r = 0; r < 4; r++)
                    yr[r] = hist + (((t0h + r0 + r) & 31) * ST_ROW);

                ull acc[4][4];
                #pragma unroll
                for (int r = 0; r < 4; r++)
                    #pragma unroll
                    for (int c = 0; c < 4; c++) acc[r][c] = 0ULL;

                #pragma unroll 4
                for (int kp = 0; kp < 32; kp++) {          // half 0: off = 2*kp
                    ulonglong2 wc0 = *(const ulonglong2*)(WcP + kp*64 + c4);
                    ulonglong2 wc1 = *(const ulonglong2*)(WcP + kp*64 + c4 + 2);
                    #pragma unroll
                    for (int r = 0; r < 4; r++) {
                        ull yv = *(const ull*)(yr[r] + 2*kp);
                        acc[r][0] = ffma2(yv, wc0.x, acc[r][0]);
                        acc[r][1] = ffma2(yv, wc0.y, acc[r][1]);
                        acc[r][2] = ffma2(yv, wc1.x, acc[r][2]);
                        acc[r][3] = ffma2(yv, wc1.y, acc[r][3]);
                    }
                }
                #pragma unroll 4
                for (int kp = 32; kp < 64; kp++) {         // half 1: off = 68+2*(kp-32)
                    ulonglong2 wc0 = *(const ulonglong2*)(WcP + kp*64 + c4);
                    ulonglong2 wc1 = *(const ulonglong2*)(WcP + kp*64 + c4 + 2);
                    #pragma unroll
                    for (int r = 0; r < 4; r++) {
                        ull yv = *(const ull*)(yr[r] + 68 + 2*(kp - 32));
                        acc[r][0] = ffma2(yv, wc0.x, acc[r][0]);
                        acc[r][1] = ffma2(yv, wc0.y, acc[r][1]);
                        acc[r][2] = ffma2(yv, wc1.x, acc[r][2]);
                        acc[r][3] = ffma2(yv, wc1.y, acc[r][3]);
                    }
                }

                #pragma unroll
                for (int r = 0; r < 4; r++) {
                    float4 o; float x, y;
                    upk2(acc[r][0], x, y); o.x = x + y + bb[0];
                    upk2(acc[r][1], x, y); o.y = x + y + bb[1];
                    upk2(acc[r][2], x, y); o.z = x + y + bb[2];
                    upk2(acc[r][3], x, y); o.w = x + y + bb[3];
                    *(float4*)(out + ((size_t)b * T_ + t0h + r0 + r) * 64 + c4) = o;
                }
            }
            __syncthreads();   // block boundary (all 192)
        }
    }
}

extern "C" void kernel_launch(void* const* d_in, const int* in_sizes, int n_in,
                              void* d_out, int out_size) {
    (void)in_sizes; (void)n_in; (void)out_size;
    const float* X  = (const float*)d_in[0];
    const float* W1 = (const float*)d_in[1];
    const float* b1 = (const float*)d_in[2];
    const float* W2 = (const float*)d_in[3];
    const float* b2 = (const float*)d_in[4];
    const float* Wc = (const float*)d_in[5];
    const float* bc = (const float*)d_in[6];
    float* out = (float*)d_out;

    cudaFuncSetAttribute(k1_in_gemm, cudaFuncAttributeMaxDynamicSharedMemorySize, 98304);
    cudaFuncSetAttribute(k2_fused,   cudaFuncAttributeMaxDynamicSharedMemorySize, 98304);

    k1_in_gemm<<<M_/64, 256, 98304>>>(X, W1, b1);

    const int k2_smem = (8192 + 32*ST_ROW + 2*2048) * 4;
    k2_fused<<<B_, 192, k2_smem>>>(W2, b2, Wc, bc, out);
}